// round 12
// baseline (speedup 1.0000x reference)
#include <cuda_runtime.h>
#include <cuda_bf16.h>

#define KE_CONST 138.96f

// Packed per-atom {charge, sys_idx-as-float-bits}. 1<<19 * 8B = 4 MB static
// scratch (allocation-free per harness rules). N in this problem is 262144.
#define QS_CAP (1 << 19)
__device__ float2 g_qs[QS_CAP];

// Grid-barrier counters. Reset protocol guarantees both are 0 at kernel exit,
// so graph replays are deterministic. A: phase-1 (pack) barrier. B: exit
// barrier, write-only for all CTAs except CTA 0 (which resets both).
__device__ unsigned g_barA;
__device__ unsigned g_barB;

__global__ void zero_out_kernel(float* __restrict__ out, int S) {
    int t = blockIdx.x * blockDim.x + threadIdx.x;
    if (t < S) out[t] = 0.0f;
}

__device__ __forceinline__ float chi_fn(float d) {
    float u  = 2.0f * d;
    float u2 = u * u;
    float u3 = u2 * u;
    // phi = 1 + u^3 * (-10 + u*(15 - 6u)), clamped to 0 for u >= 1
    float p   = fmaf(u, fmaf(u, -6.0f, 15.0f), -10.0f);
    float phi = (u < 1.0f) ? fmaf(u3, p, 1.0f) : 0.0f;
    float inv_d  = __fdividef(1.0f, d);
    float inv_rs = rsqrtf(fmaf(d, d, 1.0f));
    return fmaf(phi, inv_rs, (1.0f - phi) * inv_d);
}

__device__ __forceinline__ void process_pair(
    int i, int j, float d,
    const float* __restrict__ q,
    float* __restrict__ sbin)
{
    const bool m = (i < j);
    // Branchless predicated gathers: @P LDG keeps loads batched for MLP.
    float2 qs = m ? __ldg(&g_qs[i]) : make_float2(0.0f, 0.0f);  // one LDG.64
    float qj  = m ? __ldg(q + j) : 0.0f;
    float e   = qs.x * qj * chi_fn(d);
    if (m) atomicAdd(&sbin[__float_as_int(qs.y)], e);
}

// Single fused kernel: phase 1 packs {q,sys} and zeroes out[]; a software
// grid barrier (safe: grid == exactly one resident wave); phase 2 is the
// proven pair loop, unchanged from the 73us version.
__global__ void __launch_bounds__(256, 8)
coulomb_fused(const int*   __restrict__ pair,
              const float* __restrict__ dij,
              const float* __restrict__ q,
              const int*   __restrict__ sys,
              float*       __restrict__ out,
              int P, int N, int S)
{
    extern __shared__ float sbin[];
    for (int s = threadIdx.x; s < S; s += blockDim.x) sbin[s] = 0.0f;

    const int stride = gridDim.x * blockDim.x;
    const int gtid   = blockIdx.x * blockDim.x + threadIdx.x;

    // ---- Phase 1: pack q/sys (vectorized) + zero output ----
    const int nvecN = N >> 2;
    for (int t = gtid; t < nvecN; t += stride) {
        float4 qq = __ldg(reinterpret_cast<const float4*>(q)   + t);
        int4   ss = __ldg(reinterpret_cast<const int4*>(sys) + t);
        float4* dst = reinterpret_cast<float4*>(&g_qs[t << 2]);
        dst[0] = make_float4(qq.x, __int_as_float(ss.x), qq.y, __int_as_float(ss.y));
        dst[1] = make_float4(qq.z, __int_as_float(ss.z), qq.w, __int_as_float(ss.w));
    }
    for (int t = (nvecN << 2) + gtid; t < N; t += stride)
        g_qs[t] = make_float2(q[t], __int_as_float(sys[t]));
    for (int t = gtid; t < S; t += stride)
        out[t] = 0.0f;

    // ---- Grid barrier A ----
    __threadfence();          // make packing writes visible device-wide
    __syncthreads();          // all threads in CTA done with phase 1
    if (threadIdx.x == 0) {
        atomicAdd(&g_barA, 1u);
        while (*(volatile unsigned*)&g_barA < gridDim.x) { }
    }
    __syncthreads();
    __threadfence();          // acquire: order g_qs reads after the barrier

    // ---- Phase 2: pair loop (identical to the proven hot loop) ----
    const int4*   pi4 = reinterpret_cast<const int4*>(pair);        // idx_i row
    const int4*   pj4 = reinterpret_cast<const int4*>(pair + P);    // idx_j row
    const float4* d4  = reinterpret_cast<const float4*>(dij);
    const int nvec = P >> 2;

    for (int v = gtid; v < nvec; v += stride) {
        // Streamed once: evict-first so it doesn't thrash L2 vs the gathers.
        int4   ii = __ldcs(pi4 + v);
        int4   jj = __ldcs(pj4 + v);
        float4 dd = __ldcs(d4  + v);
        process_pair(ii.x, jj.x, dd.x, q, sbin);
        process_pair(ii.y, jj.y, dd.y, q, sbin);
        process_pair(ii.z, jj.z, dd.z, q, sbin);
        process_pair(ii.w, jj.w, dd.w, q, sbin);
    }
    for (int p = (nvec << 2) + gtid; p < P; p += stride) {
        int   i = __ldg(pair + p);
        int   j = __ldg(pair + P + p);
        float d = __ldg(dij + p);
        process_pair(i, j, d, q, sbin);
    }

    __syncthreads();

    // Flush per-CTA bins (KE scale applied once here).
    for (int s = threadIdx.x; s < S; s += blockDim.x)
        atomicAdd(&out[s], sbin[s] * KE_CONST);

    // ---- Exit protocol: reset barriers race-free for the next replay ----
    // All CTAs arrive at B (write-only) and exit. Only CTA 0 reads B; once
    // everyone has arrived (hence is past all reads of A), it resets both.
    __syncthreads();
    if (threadIdx.x == 0) {
        __threadfence();
        atomicAdd(&g_barB, 1u);
        if (blockIdx.x == 0) {
            while (*(volatile unsigned*)&g_barB < gridDim.x) { }
            *(volatile unsigned*)&g_barA = 0u;
            *(volatile unsigned*)&g_barB = 0u;
            __threadfence();
        }
    }
}

// Fallback (N > QS_CAP): original two-launch unpacked path.
__global__ void __launch_bounds__(256, 8)
coulomb_kernel_unpacked(const int*   __restrict__ pair,
                        const float* __restrict__ dij,
                        const float* __restrict__ q,
                        const int*   __restrict__ sys,
                        float*       __restrict__ out,
                        int P, int S)
{
    extern __shared__ float sbin[];
    for (int s = threadIdx.x; s < S; s += blockDim.x) sbin[s] = 0.0f;
    __syncthreads();

    const int stride = gridDim.x * blockDim.x;
    const int gtid   = blockIdx.x * blockDim.x + threadIdx.x;
    for (int p = gtid; p < P; p += stride) {
        int   i = __ldg(pair + p);
        int   j = __ldg(pair + P + p);
        float d = __ldg(dij + p);
        bool  m = i < j;
        float qi = m ? __ldg(q + i)  : 0.0f;
        float qj = m ? __ldg(q + j)  : 0.0f;
        int   s  = m ? __ldg(sys + i) : 0;
        float e  = qi * qj * chi_fn(d);
        if (m) atomicAdd(&sbin[s], e);
    }
    __syncthreads();
    for (int s = threadIdx.x; s < S; s += blockDim.x)
        atomicAdd(&out[s], sbin[s] * KE_CONST);
}

extern "C" void kernel_launch(void* const* d_in, const int* in_sizes, int n_in,
                              void* d_out, int out_size)
{
    const int*   pair = (const int*)  d_in[0];  // (2, P) int32
    const float* dij  = (const float*)d_in[1];  // (P, 1) float32
    const float* q    = (const float*)d_in[2];  // (N, 1) float32
    const int*   sys  = (const int*)  d_in[3];  // (N,)   int32
    float*       out  = (float*)d_out;

    const int P = in_sizes[1];      // number of pairs
    const int N = in_sizes[2];      // number of atoms
    const int S = out_size;         // num_systems

    const int threads = 256;
    const int blocks  = 1184;       // 8 CTAs/SM * 148 SMs == exactly one wave
    const size_t smem = (size_t)S * sizeof(float);

    if (N <= QS_CAP) {
        coulomb_fused<<<blocks, threads, smem>>>(pair, dij, q, sys, out, P, N, S);
    } else {
        zero_out_kernel<<<(S + 255) / 256, 256>>>(out, S);
        coulomb_kernel_unpacked<<<blocks, threads, smem>>>(pair, dij, q, sys, out, P, S);
    }
}

// round 15
// speedup vs baseline: 1.1866x; 1.1866x over previous
#include <cuda_runtime.h>
#include <cuda_bf16.h>

#define KE_CONST 138.96f

// Packed per-atom {charge, sys_idx-as-float-bits}. 1<<19 * 8B = 4 MB static
// scratch (allocation-free per harness rules). N in this problem is 262144.
#define QS_CAP (1 << 19)
__device__ float2 g_qs[QS_CAP];

// Vectorized pack: 4 atoms/thread, and zero the output array in the same
// launch (one graph node ahead of the main kernel instead of two).
__global__ void pack_qs_kernel(const float* __restrict__ q,
                               const int*   __restrict__ sys,
                               float* __restrict__ out,
                               int N, int S) {
    int t = blockIdx.x * blockDim.x + threadIdx.x;
    int nvec = N >> 2;
    if (t < nvec) {
        float4 qq = __ldg(reinterpret_cast<const float4*>(q) + t);
        int4   ss = __ldg(reinterpret_cast<const int4*>(sys) + t);
        float4* dst = reinterpret_cast<float4*>(&g_qs[t << 2]);
        dst[0] = make_float4(qq.x, __int_as_float(ss.x), qq.y, __int_as_float(ss.y));
        dst[1] = make_float4(qq.z, __int_as_float(ss.z), qq.w, __int_as_float(ss.w));
    }
    // Scalar tail for N % 4 != 0
    if (t < (N & 3)) {
        int tail = (nvec << 2) + t;
        g_qs[tail] = make_float2(q[tail], __int_as_float(sys[tail]));
    }
    if (t < S) out[t] = 0.0f;
}

__global__ void zero_out_kernel(float* __restrict__ out, int S) {
    int t = blockIdx.x * blockDim.x + threadIdx.x;
    if (t < S) out[t] = 0.0f;
}

__device__ __forceinline__ float chi_fn(float d) {
    float u  = 2.0f * d;
    float u2 = u * u;
    float u3 = u2 * u;
    // phi = 1 + u^3 * (-10 + u*(15 - 6u)), clamped to 0 for u >= 1
    float p   = fmaf(u, fmaf(u, -6.0f, 15.0f), -10.0f);
    float phi = (u < 1.0f) ? fmaf(u3, p, 1.0f) : 0.0f;
    float inv_d  = __fdividef(1.0f, d);
    float inv_rs = rsqrtf(fmaf(d, d, 1.0f));
    return fmaf(phi, inv_rs, (1.0f - phi) * inv_d);
}

__device__ __forceinline__ void process_pair(
    int i, int j, float d,
    const float* __restrict__ q,
    float* __restrict__ sbin)
{
    const bool m = (i < j);
    // Branchless predicated gathers: @P LDG keeps loads batched for MLP.
    float2 qs = m ? __ldg(&g_qs[i]) : make_float2(0.0f, 0.0f);  // one LDG.64
    float qj  = m ? __ldg(q + j) : 0.0f;
    float e   = qs.x * qj * chi_fn(d);
    if (m) atomicAdd(&sbin[__float_as_int(qs.y)], e);
}

// Hot kernel: identical per-thread loop to the proven 73us version, but
// 512-thread CTAs -> half the CTAs -> half the sbin zeroing and half the
// final flush atomics (both scale with CTA count, not with pair work).
__global__ void __launch_bounds__(512, 4)
coulomb_kernel(const int*   __restrict__ pair,
               const float* __restrict__ dij,
               const float* __restrict__ q,
               float*       __restrict__ out,
               int P, int S)
{
    extern __shared__ float sbin[];
    for (int s = threadIdx.x; s < S; s += blockDim.x) sbin[s] = 0.0f;
    __syncthreads();

    const int4*   pi4 = reinterpret_cast<const int4*>(pair);        // idx_i row
    const int4*   pj4 = reinterpret_cast<const int4*>(pair + P);    // idx_j row
    const float4* d4  = reinterpret_cast<const float4*>(dij);

    const int nvec   = P >> 2;
    const int stride = gridDim.x * blockDim.x;
    const int gtid   = blockIdx.x * blockDim.x + threadIdx.x;

    for (int v = gtid; v < nvec; v += stride) {
        // Streamed once: evict-first so it doesn't thrash L2 vs the gathers.
        int4   ii = __ldcs(pi4 + v);
        int4   jj = __ldcs(pj4 + v);
        float4 dd = __ldcs(d4  + v);
        process_pair(ii.x, jj.x, dd.x, q, sbin);
        process_pair(ii.y, jj.y, dd.y, q, sbin);
        process_pair(ii.z, jj.z, dd.z, q, sbin);
        process_pair(ii.w, jj.w, dd.w, q, sbin);
    }

    // Scalar tail (P % 4 != 0 insurance)
    for (int p = (nvec << 2) + gtid; p < P; p += stride) {
        int   i = __ldg(pair + p);
        int   j = __ldg(pair + P + p);
        float d = __ldg(dij + p);
        process_pair(i, j, d, q, sbin);
    }

    __syncthreads();

    // Flush per-CTA bins (KE scale applied once here).
    for (int s = threadIdx.x; s < S; s += blockDim.x)
        atomicAdd(&out[s], sbin[s] * KE_CONST);
}

// Fallback (N > QS_CAP): unpacked gathers.
__global__ void __launch_bounds__(512, 4)
coulomb_kernel_unpacked(const int*   __restrict__ pair,
                        const float* __restrict__ dij,
                        const float* __restrict__ q,
                        const int*   __restrict__ sys,
                        float*       __restrict__ out,
                        int P, int S)
{
    extern __shared__ float sbin[];
    for (int s = threadIdx.x; s < S; s += blockDim.x) sbin[s] = 0.0f;
    __syncthreads();

    const int stride = gridDim.x * blockDim.x;
    const int gtid   = blockIdx.x * blockDim.x + threadIdx.x;
    for (int p = gtid; p < P; p += stride) {
        int   i = __ldg(pair + p);
        int   j = __ldg(pair + P + p);
        float d = __ldg(dij + p);
        bool  m = i < j;
        float qi = m ? __ldg(q + i)  : 0.0f;
        float qj = m ? __ldg(q + j)  : 0.0f;
        int   s  = m ? __ldg(sys + i) : 0;
        float e  = qi * qj * chi_fn(d);
        if (m) atomicAdd(&sbin[s], e);
    }
    __syncthreads();
    for (int s = threadIdx.x; s < S; s += blockDim.x)
        atomicAdd(&out[s], sbin[s] * KE_CONST);
}

extern "C" void kernel_launch(void* const* d_in, const int* in_sizes, int n_in,
                              void* d_out, int out_size)
{
    const int*   pair = (const int*)  d_in[0];  // (2, P) int32
    const float* dij  = (const float*)d_in[1];  // (P, 1) float32
    const float* q    = (const float*)d_in[2];  // (N, 1) float32
    const int*   sys  = (const int*)  d_in[3];  // (N,)   int32
    float*       out  = (float*)d_out;

    const int P = in_sizes[1];      // number of pairs
    const int N = in_sizes[2];      // number of atoms
    const int S = out_size;         // num_systems

    const int threads = 512;
    const int blocks  = 592;        // 4 CTAs/SM * 148 SMs == exactly one wave
    const size_t smem = (size_t)S * sizeof(float);

    if (N <= QS_CAP) {
        int nvec = N >> 2;
        int work = (nvec > S ? nvec : S);
        pack_qs_kernel<<<(work + 255) / 256, 256>>>(q, sys, out, N, S);
        coulomb_kernel<<<blocks, threads, smem>>>(pair, dij, q, out, P, S);
    } else {
        zero_out_kernel<<<(S + 255) / 256, 256>>>(out, S);
        coulomb_kernel_unpacked<<<blocks, threads, smem>>>(pair, dij, q, sys, out, P, S);
    }
}

// round 16
// speedup vs baseline: 1.2213x; 1.0292x over previous
#include <cuda_runtime.h>
#include <cuda_bf16.h>

#define KE_CONST 138.96f

// Packed per-atom {charge, sys_idx-as-float-bits}. 1<<19 * 8B = 4 MB static
// scratch (allocation-free per harness rules). N in this problem is 262144.
#define QS_CAP (1 << 19)
__device__ float2 g_qs[QS_CAP];

// Vectorized pack: 4 atoms/thread, and zero the output array in the same
// launch (one graph node ahead of the main kernel instead of two).
__global__ void pack_qs_kernel(const float* __restrict__ q,
                               const int*   __restrict__ sys,
                               float* __restrict__ out,
                               int N, int S) {
    int t = blockIdx.x * blockDim.x + threadIdx.x;
    int nvec = N >> 2;
    if (t < nvec) {
        float4 qq = __ldg(reinterpret_cast<const float4*>(q) + t);
        int4   ss = __ldg(reinterpret_cast<const int4*>(sys) + t);
        float4* dst = reinterpret_cast<float4*>(&g_qs[t << 2]);
        dst[0] = make_float4(qq.x, __int_as_float(ss.x), qq.y, __int_as_float(ss.y));
        dst[1] = make_float4(qq.z, __int_as_float(ss.z), qq.w, __int_as_float(ss.w));
    }
    // Scalar tail for N % 4 != 0
    if (t < (N & 3)) {
        int tail = (nvec << 2) + t;
        g_qs[tail] = make_float2(q[tail], __int_as_float(sys[tail]));
    }
    if (t < S) out[t] = 0.0f;
}

__global__ void zero_out_kernel(float* __restrict__ out, int S) {
    int t = blockIdx.x * blockDim.x + threadIdx.x;
    if (t < S) out[t] = 0.0f;
}

__device__ __forceinline__ float chi_fn(float d) {
    float u  = 2.0f * d;
    float u2 = u * u;
    float u3 = u2 * u;
    // phi = 1 + u^3 * (-10 + u*(15 - 6u)), clamped to 0 for u >= 1
    float p   = fmaf(u, fmaf(u, -6.0f, 15.0f), -10.0f);
    float phi = (u < 1.0f) ? fmaf(u3, p, 1.0f) : 0.0f;
    float inv_d  = __fdividef(1.0f, d);
    float inv_rs = rsqrtf(fmaf(d, d, 1.0f));
    return fmaf(phi, inv_rs, (1.0f - phi) * inv_d);
}

__device__ __forceinline__ void process_pair(
    int i, int j, float d,
    const float* __restrict__ q,
    float* __restrict__ sbin)
{
    const bool m = (i < j);
    // Branchless predicated gathers: @P LDG keeps loads batched for MLP.
    float2 qs = m ? __ldg(&g_qs[i]) : make_float2(0.0f, 0.0f);  // one LDG.64
    float qj  = m ? __ldg(q + j) : 0.0f;
    float e   = qs.x * qj * chi_fn(d);
    if (m) atomicAdd(&sbin[__float_as_int(qs.y)], e);
}

// Hot kernel: identical per-thread loop to the proven version; 1024-thread
// CTAs (2 CTAs/SM, same 2048 threads/SM) -> CTA-count-proportional costs
// (sbin zeroing, flush atomics) halve again vs the 512-thread variant.
// With S == 1024 the zero/flush loops are exactly one iteration per thread.
__global__ void __launch_bounds__(1024, 2)
coulomb_kernel(const int*   __restrict__ pair,
               const float* __restrict__ dij,
               const float* __restrict__ q,
               float*       __restrict__ out,
               int P, int S)
{
    extern __shared__ float sbin[];
    for (int s = threadIdx.x; s < S; s += blockDim.x) sbin[s] = 0.0f;
    __syncthreads();

    const int4*   pi4 = reinterpret_cast<const int4*>(pair);        // idx_i row
    const int4*   pj4 = reinterpret_cast<const int4*>(pair + P);    // idx_j row
    const float4* d4  = reinterpret_cast<const float4*>(dij);

    const int nvec   = P >> 2;
    const int stride = gridDim.x * blockDim.x;
    const int gtid   = blockIdx.x * blockDim.x + threadIdx.x;

    for (int v = gtid; v < nvec; v += stride) {
        // Streamed once: evict-first so it doesn't thrash L2 vs the gathers.
        int4   ii = __ldcs(pi4 + v);
        int4   jj = __ldcs(pj4 + v);
        float4 dd = __ldcs(d4  + v);
        process_pair(ii.x, jj.x, dd.x, q, sbin);
        process_pair(ii.y, jj.y, dd.y, q, sbin);
        process_pair(ii.z, jj.z, dd.z, q, sbin);
        process_pair(ii.w, jj.w, dd.w, q, sbin);
    }

    // Scalar tail (P % 4 != 0 insurance)
    for (int p = (nvec << 2) + gtid; p < P; p += stride) {
        int   i = __ldg(pair + p);
        int   j = __ldg(pair + P + p);
        float d = __ldg(dij + p);
        process_pair(i, j, d, q, sbin);
    }

    __syncthreads();

    // Flush per-CTA bins (KE scale applied once here).
    for (int s = threadIdx.x; s < S; s += blockDim.x)
        atomicAdd(&out[s], sbin[s] * KE_CONST);
}

// Fallback (N > QS_CAP): unpacked gathers.
__global__ void __launch_bounds__(1024, 2)
coulomb_kernel_unpacked(const int*   __restrict__ pair,
                        const float* __restrict__ dij,
                        const float* __restrict__ q,
                        const int*   __restrict__ sys,
                        float*       __restrict__ out,
                        int P, int S)
{
    extern __shared__ float sbin[];
    for (int s = threadIdx.x; s < S; s += blockDim.x) sbin[s] = 0.0f;
    __syncthreads();

    const int stride = gridDim.x * blockDim.x;
    const int gtid   = blockIdx.x * blockDim.x + threadIdx.x;
    for (int p = gtid; p < P; p += stride) {
        int   i = __ldg(pair + p);
        int   j = __ldg(pair + P + p);
        float d = __ldg(dij + p);
        bool  m = i < j;
        float qi = m ? __ldg(q + i)  : 0.0f;
        float qj = m ? __ldg(q + j)  : 0.0f;
        int   s  = m ? __ldg(sys + i) : 0;
        float e  = qi * qj * chi_fn(d);
        if (m) atomicAdd(&sbin[s], e);
    }
    __syncthreads();
    for (int s = threadIdx.x; s < S; s += blockDim.x)
        atomicAdd(&out[s], sbin[s] * KE_CONST);
}

extern "C" void kernel_launch(void* const* d_in, const int* in_sizes, int n_in,
                              void* d_out, int out_size)
{
    const int*   pair = (const int*)  d_in[0];  // (2, P) int32
    const float* dij  = (const float*)d_in[1];  // (P, 1) float32
    const float* q    = (const float*)d_in[2];  // (N, 1) float32
    const int*   sys  = (const int*)  d_in[3];  // (N,)   int32
    float*       out  = (float*)d_out;

    const int P = in_sizes[1];      // number of pairs
    const int N = in_sizes[2];      // number of atoms
    const int S = out_size;         // num_systems

    const int threads = 1024;
    const int blocks  = 296;        // 2 CTAs/SM * 148 SMs == exactly one wave
    const size_t smem = (size_t)S * sizeof(float);

    if (N <= QS_CAP) {
        int nvec = N >> 2;
        int work = (nvec > S ? nvec : S);
        pack_qs_kernel<<<(work + 255) / 256, 256>>>(q, sys, out, N, S);
        coulomb_kernel<<<blocks, threads, smem>>>(pair, dij, q, out, P, S);
    } else {
        zero_out_kernel<<<(S + 255) / 256, 256>>>(out, S);
        coulomb_kernel_unpacked<<<blocks, threads, smem>>>(pair, dij, q, sys, out, P, S);
    }
}